// round 10
// baseline (speedup 1.0000x reference)
#include <cuda_runtime.h>
#include <cuda_bf16.h>
#include <cstdint>

#define F 128
#define MAXN 50048
#define MAXE 1048576

// Device-global scratch. Never referenced from host; all atomics target these.
__device__ __align__(16) float g_h[(size_t)MAXN * F];     // hs = h*dinv (gather src)
__device__ __align__(16) float g_out1[(size_t)MAXN * F];  // relu(layer-1) result
__device__ __align__(16) int2 g_edge[MAXE];               // decoded (src,dst) cache
__device__ float g_dinv[MAXN];
__device__ int   g_deg[MAXN];
__device__ int   g_off[MAXN + 1];   // CSR row offsets (by dst)
__device__ int   g_cur[MAXN];       // build cursors
__device__ int   g_csr_src[MAXE];   // src node per CSR slot
__device__ int   g_is64;

// ---------------------------------------------------------------------------
// init: zero degrees; block 0 detects edge dtype in parallel
// (int64 little-endian => odd int32 words of first 64 entries are all zero)
// ---------------------------------------------------------------------------
__global__ void init_kernel(const int* __restrict__ ei32, int N) {
    int i = blockIdx.x * blockDim.x + threadIdx.x;
    if (i < N) g_deg[i] = 0;

    if (blockIdx.x == 0) {
        __shared__ int nz[64];
        int t = threadIdx.x;
        if (t < 64) nz[t] = (ei32[2 * t + 1] != 0);
        __syncthreads();
        if (t == 0) {
            int any = 0;
#pragma unroll
            for (int k = 0; k < 64; k++) any |= nz[k];
            g_is64 = any ? 0 : 1;
        }
    }
}

__device__ __forceinline__ int edge_at(const int* __restrict__ ei32,
                                       long long idx, int is64) {
    if (is64) return (int)__ldg(((const long long*)ei32) + idx);
    return __ldg(ei32 + idx);
}

// ---------------------------------------------------------------------------
// degree count + edge decode cache (single read of the raw edge list)
// ---------------------------------------------------------------------------
__global__ void count_decode_kernel(const int* __restrict__ ei, int E, int N) {
    int e = blockIdx.x * blockDim.x + threadIdx.x;
    if (e < E) {
        int is64 = g_is64;
        int src = edge_at(ei, e, is64);
        int dst = edge_at(ei, (long long)E + e, is64);
        g_edge[e] = make_int2(src, dst);
        if ((unsigned)dst < (unsigned)N)
            atomicAdd(&g_deg[dst], 1);
    }
}

// ---------------------------------------------------------------------------
// Single-block scan of g_deg -> g_off/g_cur, fused with dinv computation.
// ---------------------------------------------------------------------------
__global__ __launch_bounds__(1024)
void scan_dinv_kernel(int N) {
    __shared__ int sums[1024];
    int t = threadIdx.x;
    int chunk = (N + 1023) / 1024;
    int lo = t * chunk;
    int hi = min(lo + chunk, N);
    int s = 0;
    for (int i = lo; i < hi; i++) s += g_deg[i];
    sums[t] = s;
    __syncthreads();
    for (int d = 1; d < 1024; d <<= 1) {
        int v = (t >= d) ? sums[t - d] : 0;
        __syncthreads();
        sums[t] += v;
        __syncthreads();
    }
    int base = (t == 0) ? 0 : sums[t - 1];
    for (int i = lo; i < hi; i++) {
        int dg = g_deg[i];
        g_off[i] = base;
        g_cur[i] = base;
        g_dinv[i] = rsqrtf((float)(dg + 1));  // +1 = self-loop
        base += dg;
    }
    if (hi == N && lo <= N) g_off[N] = base;
}

// CSR placement from the compact decoded cache (src only; norms factored out).
__global__ void build_csr_kernel(int E, int N) {
    int e = blockIdx.x * blockDim.x + threadIdx.x;
    if (e >= E) return;
    int2 ed = g_edge[e];
    if ((unsigned)ed.x >= (unsigned)N || (unsigned)ed.y >= (unsigned)N) return;
    int pos = atomicAdd(&g_cur[ed.y], 1);
    g_csr_src[pos] = ed.x;
}

// ---------------------------------------------------------------------------
// TF32 tensor-core GEMM (no reg prefetch; keeps 2 CTAs/SM).
// LAYER 0: hs = (Xext@W)*dinv ; LAYER 1: hs = (g_out1@W)*dinv
// BM=128, BN=128(=F), BK=32.  256 thr = 8 warps in 4x2; warp tile 32x64.
// ---------------------------------------------------------------------------
__device__ __forceinline__ uint32_t f2tf32(float f) {
    uint32_t r;
    asm("cvt.rna.tf32.f32 %0, %1;" : "=r"(r) : "f"(f));
    return r;
}

__device__ __forceinline__ void mma_tf32(float* c, const uint32_t* a,
                                         const uint32_t* b) {
    asm volatile(
        "mma.sync.aligned.m16n8k8.row.col.f32.tf32.tf32.f32 "
        "{%0,%1,%2,%3}, {%4,%5,%6,%7}, {%8,%9}, {%0,%1,%2,%3};\n"
        : "+f"(c[0]), "+f"(c[1]), "+f"(c[2]), "+f"(c[3])
        : "r"(a[0]), "r"(a[1]), "r"(a[2]), "r"(a[3]), "r"(b[0]), "r"(b[1]));
}

template <int LAYER>
__global__ __launch_bounds__(256)
void gemm_kernel(const float* __restrict__ Xext, const float* __restrict__ W,
                 int N) {
    // pads: 33 % 32 == 1 and 136 % 32 == 8 -> conflict-free fragment loads
    __shared__ uint32_t As[128][33];
    __shared__ uint32_t Bs[32][136];

    const float* X = (LAYER == 0) ? Xext : g_out1;

    const int tid = threadIdx.x;
    const int wid = tid >> 5;
    const int lane = tid & 31;
    const int wm = wid & 3;            // 0..3 -> 32-row band
    const int wn = wid >> 2;           // 0..1 -> 64-col band
    const int row0 = blockIdx.x * 128;

    float acc[2][8][4];
#pragma unroll
    for (int mt = 0; mt < 2; mt++)
#pragma unroll
        for (int j = 0; j < 8; j++)
#pragma unroll
            for (int q = 0; q < 4; q++) acc[mt][j][q] = 0.0f;

    for (int kc = 0; kc < 4; kc++) {
        const int k0 = kc * 32;
        // --- A tile: 128x32 floats = 1024 float4 = 256 thr * 4 ---
#pragma unroll
        for (int l = 0; l < 4; l++) {
            int f4 = tid + l * 256;
            int r = f4 >> 3;
            int c4 = (f4 & 7) * 4;
            int grow = row0 + r;
            float4 v = make_float4(0.f, 0.f, 0.f, 0.f);
            if (grow < N) v = *(const float4*)(X + (size_t)grow * F + k0 + c4);
            As[r][c4] = f2tf32(v.x); As[r][c4 + 1] = f2tf32(v.y);
            As[r][c4 + 2] = f2tf32(v.z); As[r][c4 + 3] = f2tf32(v.w);
        }
        // --- B tile: 32x128 floats = 1024 float4 = 256 thr * 4 ---
#pragma unroll
        for (int l = 0; l < 4; l++) {
            int f4 = tid + l * 256;
            int r = f4 >> 5;
            int c4 = (f4 & 31) * 4;
            float4 v = *(const float4*)(W + (size_t)(k0 + r) * F + c4);
            Bs[r][c4] = f2tf32(v.x); Bs[r][c4 + 1] = f2tf32(v.y);
            Bs[r][c4 + 2] = f2tf32(v.z); Bs[r][c4 + 3] = f2tf32(v.w);
        }
        __syncthreads();

#pragma unroll
        for (int ks = 0; ks < 4; ks++) {
            const int kk = ks * 8;
            const int g = lane >> 2;
            const int r4 = lane & 3;
            uint32_t a[2][4];
#pragma unroll
            for (int mt = 0; mt < 2; mt++) {
                int ar = wm * 32 + mt * 16 + g;
                a[mt][0] = As[ar][kk + r4];
                a[mt][1] = As[ar + 8][kk + r4];
                a[mt][2] = As[ar][kk + r4 + 4];
                a[mt][3] = As[ar + 8][kk + r4 + 4];
            }
            uint32_t b[8][2];
#pragma unroll
            for (int j = 0; j < 8; j++) {
                int bc = wn * 64 + j * 8 + g;
                b[j][0] = Bs[kk + r4][bc];
                b[j][1] = Bs[kk + r4 + 4][bc];
            }
#pragma unroll
            for (int mt = 0; mt < 2; mt++)
#pragma unroll
                for (int j = 0; j < 8; j++)
                    mma_tf32(acc[mt][j], a[mt], b[j]);
        }
        __syncthreads();
    }

    // epilogue: scale by dinv[row] -> store hs = h*dinv
    const int g = lane >> 2;
    const int r4 = lane & 3;
#pragma unroll
    for (int mt = 0; mt < 2; mt++) {
        int row = row0 + wm * 32 + mt * 16 + g;
        float d0 = (row < N) ? g_dinv[row] : 0.f;
        float d1 = (row + 8 < N) ? g_dinv[row + 8] : 0.f;
#pragma unroll
        for (int j = 0; j < 8; j++) {
            int col = wn * 64 + j * 8 + r4 * 2;
            if (row < N)
                *(float2*)(g_h + (size_t)row * F + col) =
                    make_float2(acc[mt][j][0] * d0, acc[mt][j][1] * d0);
            if (row + 8 < N)
                *(float2*)(g_h + (size_t)(row + 8) * F + col) =
                    make_float2(acc[mt][j][2] * d1, acc[mt][j][3] * d1);
        }
    }
}

// ---------------------------------------------------------------------------
// Gather: one warp per dst node, zero atomics, no per-edge norms:
//   out[n] = relu(bias + dinv[n] * (hs[n] + sum_{e in CSR[n]} hs[src_e]))
// 8-wide unrolled edge loop for memory-level parallelism.
// ---------------------------------------------------------------------------
template <int LAYER>
__global__ __launch_bounds__(256)
void gather_kernel(const float* __restrict__ bias, float* __restrict__ out_ext,
                   int N) {
    int w = (blockIdx.x * blockDim.x + threadIdx.x) >> 5;
    int lane = threadIdx.x & 31;
    if (w >= N) return;

    const int c = lane * 4;
    const int off = g_off[w];
    const int end = g_off[w + 1];

    float4 acc = *(const float4*)(g_h + (size_t)w * F + c);  // hs[n] self term

    int e = off;
    for (; e + 7 < end; e += 8) {
        int s[8];
#pragma unroll
        for (int q = 0; q < 8; q++) s[q] = g_csr_src[e + q];
        float4 v[8];
#pragma unroll
        for (int q = 0; q < 8; q++)
            v[q] = *(const float4*)(g_h + (size_t)s[q] * F + c);
#pragma unroll
        for (int q = 0; q < 8; q++) {
            acc.x += v[q].x; acc.y += v[q].y; acc.z += v[q].z; acc.w += v[q].w;
        }
    }
    for (; e + 1 < end; e += 2) {
        int s0 = g_csr_src[e], s1 = g_csr_src[e + 1];
        float4 v0 = *(const float4*)(g_h + (size_t)s0 * F + c);
        float4 v1 = *(const float4*)(g_h + (size_t)s1 * F + c);
        acc.x += v0.x + v1.x; acc.y += v0.y + v1.y;
        acc.z += v0.z + v1.z; acc.w += v0.w + v1.w;
    }
    if (e < end) {
        int s0 = g_csr_src[e];
        float4 v0 = *(const float4*)(g_h + (size_t)s0 * F + c);
        acc.x += v0.x; acc.y += v0.y; acc.z += v0.z; acc.w += v0.w;
    }

    float d = g_dinv[w];
    float4 bv = *(const float4*)(bias + c);
    float4 r = make_float4(fmaxf(bv.x + d * acc.x, 0.f),
                           fmaxf(bv.y + d * acc.y, 0.f),
                           fmaxf(bv.z + d * acc.z, 0.f),
                           fmaxf(bv.w + d * acc.w, 0.f));

    if (LAYER == 1)
        *(float4*)(out_ext + (size_t)w * F + c) = r;   // plain STG to d_out
    else
        *(float4*)(g_out1 + (size_t)w * F + c) = r;    // already relu'd
}

extern "C" void kernel_launch(void* const* d_in, const int* in_sizes, int n_in,
                              void* d_out, int out_size) {
    const float* x = (const float*)d_in[0];
    const int* ei = (const int*)d_in[1];   // int32 or int64, detected on device
    const float* W1 = (const float*)d_in[2];
    const float* b1 = (const float*)d_in[3];
    const float* W2 = (const float*)d_in[4];
    const float* b2 = (const float*)d_in[5];
    float* out = (float*)d_out;

    int N = in_sizes[0] / F;
    int E = in_sizes[1] / 2;

    // --- CSR build (shared by both layers) ---
    init_kernel<<<(N + 255) / 256, 256>>>(ei, N);
    count_decode_kernel<<<(E + 255) / 256, 256>>>(ei, E, N);
    scan_dinv_kernel<<<1, 1024>>>(N);
    build_csr_kernel<<<(E + 255) / 256, 256>>>(E, N);

    int gemm_grid = (N + 127) / 128;
    int gath_grid = (N * 32 + 255) / 256;

    // --- layer 1 ---
    gemm_kernel<0><<<gemm_grid, 256>>>(x, W1, N);
    gather_kernel<0><<<gath_grid, 256>>>(b1, nullptr, N);

    // --- layer 2 (direct store to d_out) ---
    gemm_kernel<1><<<gemm_grid, 256>>>(nullptr, W2, N);
    gather_kernel<1><<<gath_grid, 256>>>(b2, out, N);
}

// round 11
// speedup vs baseline: 1.0446x; 1.0446x over previous
#include <cuda_runtime.h>
#include <cuda_fp16.h>
#include <cstdint>

#define F 128
#define MAXN 50048
#define MAXE 1048576

// Device-global scratch. Never referenced from host; all atomics target these.
// hs = (X@W)*dinv stored as fp16 pairs: 64 half2 per row (128 cols).
__device__ __align__(16) __half2 g_hs[(size_t)MAXN * 64];
__device__ __align__(16) float g_out1[(size_t)MAXN * F];  // relu(layer-1), fp32
__device__ float g_dinv[MAXN];
__device__ int   g_deg[MAXN];
__device__ int   g_off[MAXN + 1];   // CSR row offsets (by dst)
__device__ int   g_cur[MAXN];       // build cursors
__device__ int   g_csr_src[MAXE];   // src node per CSR slot
__device__ int   g_is64;

struct __align__(8) h4 { __half2 a, b; };   // 4 fp16 values = 8 bytes

// ---------------------------------------------------------------------------
// init: zero degrees; block 0 detects edge dtype in parallel
// (int64 little-endian => odd int32 words of first 64 entries are all zero)
// ---------------------------------------------------------------------------
__global__ void init_kernel(const int* __restrict__ ei32, int N) {
    int i = blockIdx.x * blockDim.x + threadIdx.x;
    if (i < N) g_deg[i] = 0;

    if (blockIdx.x == 0) {
        __shared__ int nz[64];
        int t = threadIdx.x;
        if (t < 64) nz[t] = (ei32[2 * t + 1] != 0);
        __syncthreads();
        if (t == 0) {
            int any = 0;
#pragma unroll
            for (int k = 0; k < 64; k++) any |= nz[k];
            g_is64 = any ? 0 : 1;
        }
    }
}

__device__ __forceinline__ int edge_at(const int* __restrict__ ei32,
                                       long long idx, int is64) {
    if (is64) return (int)__ldg(((const long long*)ei32) + idx);
    return __ldg(ei32 + idx);
}

// ---------------------------------------------------------------------------
// degree count
// ---------------------------------------------------------------------------
__global__ void count_deg_kernel(const int* __restrict__ ei, int E, int N) {
    int e = blockIdx.x * blockDim.x + threadIdx.x;
    if (e < E) {
        int is64 = g_is64;
        int dst = edge_at(ei, (long long)E + e, is64);
        if ((unsigned)dst < (unsigned)N)
            atomicAdd(&g_deg[dst], 1);
    }
}

// ---------------------------------------------------------------------------
// Single-block scan of g_deg -> g_off/g_cur, fused with dinv computation.
// ---------------------------------------------------------------------------
__global__ __launch_bounds__(1024)
void scan_dinv_kernel(int N) {
    __shared__ int sums[1024];
    int t = threadIdx.x;
    int chunk = (N + 1023) / 1024;
    int lo = t * chunk;
    int hi = min(lo + chunk, N);
    int s = 0;
    for (int i = lo; i < hi; i++) s += g_deg[i];
    sums[t] = s;
    __syncthreads();
    for (int d = 1; d < 1024; d <<= 1) {
        int v = (t >= d) ? sums[t - d] : 0;
        __syncthreads();
        sums[t] += v;
        __syncthreads();
    }
    int base = (t == 0) ? 0 : sums[t - 1];
    for (int i = lo; i < hi; i++) {
        int dg = g_deg[i];
        g_off[i] = base;
        g_cur[i] = base;
        g_dinv[i] = rsqrtf((float)(dg + 1));  // +1 = self-loop
        base += dg;
    }
    if (hi == N && lo <= N) g_off[N] = base;
}

// CSR placement (src only — norms factored out algebraically).
__global__ void build_csr_kernel(const int* __restrict__ ei, int E, int N) {
    int e = blockIdx.x * blockDim.x + threadIdx.x;
    if (e >= E) return;
    int is64 = g_is64;
    int src = edge_at(ei, e, is64);
    int dst = edge_at(ei, (long long)E + e, is64);
    if ((unsigned)src >= (unsigned)N || (unsigned)dst >= (unsigned)N) return;
    int pos = atomicAdd(&g_cur[dst], 1);
    g_csr_src[pos] = src;
}

// ---------------------------------------------------------------------------
// TF32 tensor-core GEMM; epilogue stores hs = (X@W)*dinv as fp16 (half2).
// LAYER 0: X = x (input) ; LAYER 1: X = g_out1 (already relu'd fp32).
// BM=128, BN=128(=F), BK=32.  256 thr = 8 warps in 4x2; warp tile 32x64.
// ---------------------------------------------------------------------------
__device__ __forceinline__ uint32_t f2tf32(float f) {
    uint32_t r;
    asm("cvt.rna.tf32.f32 %0, %1;" : "=r"(r) : "f"(f));
    return r;
}

__device__ __forceinline__ void mma_tf32(float* c, const uint32_t* a,
                                         const uint32_t* b) {
    asm volatile(
        "mma.sync.aligned.m16n8k8.row.col.f32.tf32.tf32.f32 "
        "{%0,%1,%2,%3}, {%4,%5,%6,%7}, {%8,%9}, {%0,%1,%2,%3};\n"
        : "+f"(c[0]), "+f"(c[1]), "+f"(c[2]), "+f"(c[3])
        : "r"(a[0]), "r"(a[1]), "r"(a[2]), "r"(a[3]), "r"(b[0]), "r"(b[1]));
}

template <int LAYER>
__global__ __launch_bounds__(256)
void gemm_kernel(const float* __restrict__ Xext, const float* __restrict__ W,
                 int N) {
    // pads: 33 % 32 == 1 and 136 % 32 == 8 -> conflict-free fragment loads
    __shared__ uint32_t As[128][33];
    __shared__ uint32_t Bs[32][136];

    const float* X = (LAYER == 0) ? Xext : g_out1;

    const int tid = threadIdx.x;
    const int wid = tid >> 5;
    const int lane = tid & 31;
    const int wm = wid & 3;            // 0..3 -> 32-row band
    const int wn = wid >> 2;           // 0..1 -> 64-col band
    const int row0 = blockIdx.x * 128;

    float acc[2][8][4];
#pragma unroll
    for (int mt = 0; mt < 2; mt++)
#pragma unroll
        for (int j = 0; j < 8; j++)
#pragma unroll
            for (int q = 0; q < 4; q++) acc[mt][j][q] = 0.0f;

    for (int kc = 0; kc < 4; kc++) {
        const int k0 = kc * 32;
        // --- A tile: 128x32 floats = 1024 float4 = 256 thr * 4 ---
#pragma unroll
        for (int l = 0; l < 4; l++) {
            int f4 = tid + l * 256;
            int r = f4 >> 3;
            int c4 = (f4 & 7) * 4;
            int grow = row0 + r;
            float4 v = make_float4(0.f, 0.f, 0.f, 0.f);
            if (grow < N) v = *(const float4*)(X + (size_t)grow * F + k0 + c4);
            As[r][c4] = f2tf32(v.x); As[r][c4 + 1] = f2tf32(v.y);
            As[r][c4 + 2] = f2tf32(v.z); As[r][c4 + 3] = f2tf32(v.w);
        }
        // --- B tile: 32x128 floats = 1024 float4 = 256 thr * 4 ---
#pragma unroll
        for (int l = 0; l < 4; l++) {
            int f4 = tid + l * 256;
            int r = f4 >> 5;
            int c4 = (f4 & 31) * 4;
            float4 v = *(const float4*)(W + (size_t)(k0 + r) * F + c4);
            Bs[r][c4] = f2tf32(v.x); Bs[r][c4 + 1] = f2tf32(v.y);
            Bs[r][c4 + 2] = f2tf32(v.z); Bs[r][c4 + 3] = f2tf32(v.w);
        }
        __syncthreads();

#pragma unroll
        for (int ks = 0; ks < 4; ks++) {
            const int kk = ks * 8;
            const int g = lane >> 2;
            const int r4 = lane & 3;
            uint32_t a[2][4];
#pragma unroll
            for (int mt = 0; mt < 2; mt++) {
                int ar = wm * 32 + mt * 16 + g;
                a[mt][0] = As[ar][kk + r4];
                a[mt][1] = As[ar + 8][kk + r4];
                a[mt][2] = As[ar][kk + r4 + 4];
                a[mt][3] = As[ar + 8][kk + r4 + 4];
            }
            uint32_t b[8][2];
#pragma unroll
            for (int j = 0; j < 8; j++) {
                int bc = wn * 64 + j * 8 + g;
                b[j][0] = Bs[kk + r4][bc];
                b[j][1] = Bs[kk + r4 + 4][bc];
            }
#pragma unroll
            for (int mt = 0; mt < 2; mt++)
#pragma unroll
                for (int j = 0; j < 8; j++)
                    mma_tf32(acc[mt][j], a[mt], b[j]);
        }
        __syncthreads();
    }

    // epilogue: hs = acc*dinv[row], stored as half2 (col pairs are even-based)
    const int g = lane >> 2;
    const int r4 = lane & 3;
#pragma unroll
    for (int mt = 0; mt < 2; mt++) {
        int row = row0 + wm * 32 + mt * 16 + g;
        float d0 = (row < N) ? g_dinv[row] : 0.f;
        float d1 = (row + 8 < N) ? g_dinv[row + 8] : 0.f;
#pragma unroll
        for (int j = 0; j < 8; j++) {
            int col = wn * 64 + j * 8 + r4 * 2;   // always even
            if (row < N)
                g_hs[(size_t)row * 64 + (col >> 1)] =
                    __floats2half2_rn(acc[mt][j][0] * d0, acc[mt][j][1] * d0);
            if (row + 8 < N)
                g_hs[(size_t)(row + 8) * 64 + (col >> 1)] =
                    __floats2half2_rn(acc[mt][j][2] * d1, acc[mt][j][3] * d1);
        }
    }
}

// ---------------------------------------------------------------------------
// Gather: one warp per dst node, zero atomics, fp32 accumulation:
//   out[n] = relu(bias + dinv[n] * (hs[n] + sum_{e in CSR[n]} hs[src_e]))
// Each lane handles 4 cols = one 8-byte h4 load per row. 4-wide edge unroll.
// ---------------------------------------------------------------------------
template <int LAYER>
__global__ __launch_bounds__(256)
void gather_kernel(const float* __restrict__ bias, float* __restrict__ out_ext,
                   int N) {
    int w = (blockIdx.x * blockDim.x + threadIdx.x) >> 5;
    int lane = threadIdx.x & 31;
    if (w >= N) return;

    const int c2 = lane * 2;           // half2 index within row (64 per row)
    const int off = g_off[w];
    const int end = g_off[w + 1];

    h4 hv = *(const h4*)(g_hs + (size_t)w * 64 + c2);   // self term
    float2 fa = __half22float2(hv.a);
    float2 fb = __half22float2(hv.b);
    float4 acc = make_float4(fa.x, fa.y, fb.x, fb.y);

    int e = off;
    for (; e + 3 < end; e += 4) {
        int s0 = g_csr_src[e], s1 = g_csr_src[e + 1];
        int s2 = g_csr_src[e + 2], s3 = g_csr_src[e + 3];
        h4 v0 = *(const h4*)(g_hs + (size_t)s0 * 64 + c2);
        h4 v1 = *(const h4*)(g_hs + (size_t)s1 * 64 + c2);
        h4 v2 = *(const h4*)(g_hs + (size_t)s2 * 64 + c2);
        h4 v3 = *(const h4*)(g_hs + (size_t)s3 * 64 + c2);
        float2 a0 = __half22float2(v0.a), b0 = __half22float2(v0.b);
        float2 a1 = __half22float2(v1.a), b1 = __half22float2(v1.b);
        float2 a2 = __half22float2(v2.a), b2 = __half22float2(v2.b);
        float2 a3 = __half22float2(v3.a), b3 = __half22float2(v3.b);
        acc.x += a0.x + a1.x + a2.x + a3.x;
        acc.y += a0.y + a1.y + a2.y + a3.y;
        acc.z += b0.x + b1.x + b2.x + b3.x;
        acc.w += b0.y + b1.y + b2.y + b3.y;
    }
    for (; e < end; e++) {
        int s0 = g_csr_src[e];
        h4 v0 = *(const h4*)(g_hs + (size_t)s0 * 64 + c2);
        float2 a0 = __half22float2(v0.a), b0 = __half22float2(v0.b);
        acc.x += a0.x; acc.y += a0.y; acc.z += b0.x; acc.w += b0.y;
    }

    float d = g_dinv[w];
    const int c = lane * 4;
    float4 bv = *(const float4*)(bias + c);
    float4 r = make_float4(fmaxf(bv.x + d * acc.x, 0.f),
                           fmaxf(bv.y + d * acc.y, 0.f),
                           fmaxf(bv.z + d * acc.z, 0.f),
                           fmaxf(bv.w + d * acc.w, 0.f));

    if (LAYER == 1)
        *(float4*)(out_ext + (size_t)w * F + c) = r;   // plain STG to d_out
    else
        *(float4*)(g_out1 + (size_t)w * F + c) = r;    // fp32, already relu'd
}

extern "C" void kernel_launch(void* const* d_in, const int* in_sizes, int n_in,
                              void* d_out, int out_size) {
    const float* x = (const float*)d_in[0];
    const int* ei = (const int*)d_in[1];   // int32 or int64, detected on device
    const float* W1 = (const float*)d_in[2];
    const float* b1 = (const float*)d_in[3];
    const float* W2 = (const float*)d_in[4];
    const float* b2 = (const float*)d_in[5];
    float* out = (float*)d_out;

    int N = in_sizes[0] / F;
    int E = in_sizes[1] / 2;

    // --- CSR build (shared by both layers) ---
    init_kernel<<<(N + 255) / 256, 256>>>(ei, N);
    count_deg_kernel<<<(E + 255) / 256, 256>>>(ei, E, N);
    scan_dinv_kernel<<<1, 1024>>>(N);
    build_csr_kernel<<<(E + 255) / 256, 256>>>(ei, E, N);

    int gemm_grid = (N + 127) / 128;
    int gath_grid = (N * 32 + 255) / 256;

    // --- layer 1 ---
    gemm_kernel<0><<<gemm_grid, 256>>>(x, W1, N);
    gather_kernel<0><<<gath_grid, 256>>>(b1, nullptr, N);

    // --- layer 2 (direct store to d_out) ---
    gemm_kernel<1><<<gemm_grid, 256>>>(nullptr, W2, N);
    gather_kernel<1><<<gath_grid, 256>>>(b2, out, N);
}